// round 8
// baseline (speedup 1.0000x reference)
#include <cuda_runtime.h>

// KAN_Convolutional_Layer: B=8, CIN=4, H=W=64, OUT=8, K2=9, G=8, Ho=Wo=62
// R8: single-wave, double-resident fused kernel.
//   grid (4,8,8)=256 blocks x 512 threads, 2 blocks/SM resident (one wave).
//   tile 16x8; thread = 4-px strip x 8 outputs x 2 of 32 (c,g) planes
//   (16-way cg split, q = lane>>1). All 32 t-planes in smem, ONE barrier.
//   Dup'd weights (w,w) -> fma2(px_pair, w_dup) = 2 px/op.
//   4-level butterfly reduction; each lane stores one (o, px-pair).

#define B_    8
#define CIN_  4
#define H_    64
#define W_    64
#define OUT_  8
#define K2_   9
#define G_    8
#define HO_   62
#define WO_   62
#define R2_   39.0625f     // R^2 folded into weights

#define TILW  20           // 16 px + 2 halo + 2 pad (float4 alignment)
#define TILH  10           // 8 rows + 2 halo
#define NPOS  (TILH*TILW)  // 200
#define PSTR  208          // plane stride words; 208 % 32 == 16 (R6 residue)
#define WCG   144          // dup'd weight stride (9*16), R6 empirical
#define NTHR  512

typedef unsigned long long u64;

__device__ __forceinline__ u64 pack2(float lo, float hi) {
    u64 r;
    asm("mov.b64 %0, {%1, %2};" : "=l"(r) : "f"(lo), "f"(hi));
    return r;
}
__device__ __forceinline__ void unpack2(u64 v, float& lo, float& hi) {
    asm("mov.b64 {%0, %1}, %2;" : "=f"(lo), "=f"(hi) : "l"(v));
}
__device__ __forceinline__ u64 fma2(u64 a, u64 b, u64 c) {
    u64 d;
    asm("fma.rn.f32x2 %0, %1, %2, %3;" : "=l"(d) : "l"(a), "l"(b), "l"(c));
    return d;
}
__device__ __forceinline__ u64 add2(u64 a, u64 b) {
    u64 d;
    asm("add.rn.f32x2 %0, %1, %2;" : "=l"(d) : "l"(a), "l"(b));
    return d;
}

__global__ void __launch_bounds__(NTHR, 2)
kan_fused_kernel(const float* __restrict__ x,
                 const float* __restrict__ phase_low,
                 const float* __restrict__ phase_high,
                 const float* __restrict__ weight,
                 const float* __restrict__ bias,
                 float* __restrict__ out) {
    __shared__ __align__(16) float tsh[32 * PSTR];   // 26.0 KB, all 32 planes
    __shared__ __align__(16) float wsh[32 * WCG];    // 18.4 KB, dup'd weights
    __shared__ float bsh[OUT_];

    const int b   = blockIdx.z;
    const int x0  = blockIdx.x * 16;
    const int y0  = blockIdx.y * 8;
    const int tid = threadIdx.x;

    // ---- duplicated weights: wsh[cg*WCG + f*16 + o*2 + {0,1}] = w*R^2
#pragma unroll
    for (int it = 0; it < 5; it++) {
        int i = tid + it * NTHR;
        if (i < 32 * K2_ * OUT_) {
            int o  = i & 7;
            int f  = (i >> 3) % K2_;
            int cg = i / (K2_ * OUT_);
            int g  = cg & 7;
            int c  = cg >> 3;
            float wv = weight[((o * CIN_ + c) * K2_ + f) * G_ + g] * R2_;
            int base = cg * WCG + f * 16 + o * 2;
            wsh[base]     = wv;
            wsh[base + 1] = wv;
        }
    }
    if (tid < OUT_) {
        float s = 0.0f;
#pragma unroll
        for (int c = 0; c < CIN_; c++) s += bias[tid * CIN_ + c];
        bsh[tid] = s;
    }

    // ---- spline fill: 4 c-planes x 200 positions -> 32 g-planes
    {
        float pl[G_], ph[G_];
#pragma unroll
        for (int g = 0; g < G_; g++) {
            pl[g] = __ldg(&phase_low[g]);   // broadcast over (o,c,f) by construction
            ph[g] = __ldg(&phase_high[g]);
        }
#pragma unroll
        for (int it = 0; it < 2; it++) {
            int i = tid + it * NTHR;
            if (i < CIN_ * NPOS) {
                int c   = i / NPOS;
                int pos = i - c * NPOS;
                int row = pos / TILW;
                int col = pos - row * TILW;
                int gy = y0 + row, gx = x0 + col;
                float xv = 0.0f;
                if (gy < H_ && gx < W_)
                    xv = __ldg(&x[((b * CIN_ + c) * H_ + gy) * W_ + gx]);
#pragma unroll
                for (int g = 0; g < G_; g++) {
                    float a = fmaxf(xv - pl[g], 0.0f);
                    float d = fmaxf(ph[g] - xv, 0.0f);
                    float m = a * d;
                    tsh[(c * G_ + g) * PSTR + pos] = m * m;   // R^2 in weights
                }
            }
        }
    }
    __syncthreads();   // the only barrier

    // ---- lane decomposition
    const int w     = tid >> 5;          // warp 0..15
    const int l     = tid & 31;
    const int q     = l >> 1;            // cg group 0..15 -> planes q, q+16
    const int sub   = l & 1;
    const int strip = w * 2 + sub;       // 0..31
    const int sy    = strip >> 2;        // row 0..7
    const int sxs   = strip & 3;         // strip col 0..3 -> px 4*sxs..4*sxs+3

    u64 acc[16];                         // [o*2 + pair]
#pragma unroll
    for (int k = 0; k < 16; k++) acc[k] = 0;

#pragma unroll
    for (int i = 0; i < 2; i++) {
        const int p = q + 16 * i;
        const float* pb = tsh + p * PSTR + sy * TILW + 4 * sxs;  // 16B aligned
        const float* wp = wsh + p * WCG;

#pragma unroll
        for (int fi = 0; fi < 3; fi++) {
            // row fi only: 6 values -> 5 px-pairs (row-streamed, low reg pressure)
            float4 v4 = *reinterpret_cast<const float4*>(pb + fi * TILW);
            float2 v2 = *reinterpret_cast<const float2*>(pb + fi * TILW + 4);
            u64 p01 = pack2(v4.x, v4.y);
            u64 p12 = pack2(v4.y, v4.z);
            u64 p23 = pack2(v4.z, v4.w);
            u64 p34 = pack2(v4.w, v2.x);
            u64 p45 = pack2(v2.x, v2.y);
            u64 pA[3] = {p01, p12, p23};   // (px0,px1) per fj
            u64 pB[3] = {p23, p34, p45};   // (px2,px3) per fj

#pragma unroll
            for (int fj = 0; fj < 3; fj++) {
                const ulonglong2* wv =
                    reinterpret_cast<const ulonglong2*>(wp + (fi * 3 + fj) * 16);
                ulonglong2 w01 = wv[0];   // dup'd o0, o1
                ulonglong2 w23 = wv[1];
                ulonglong2 w45 = wv[2];
                ulonglong2 w67 = wv[3];
                u64 ta = pA[fj];
                u64 tb = pB[fj];
                acc[0]  = fma2(ta, w01.x, acc[0]);
                acc[1]  = fma2(tb, w01.x, acc[1]);
                acc[2]  = fma2(ta, w01.y, acc[2]);
                acc[3]  = fma2(tb, w01.y, acc[3]);
                acc[4]  = fma2(ta, w23.x, acc[4]);
                acc[5]  = fma2(tb, w23.x, acc[5]);
                acc[6]  = fma2(ta, w23.y, acc[6]);
                acc[7]  = fma2(tb, w23.y, acc[7]);
                acc[8]  = fma2(ta, w45.x, acc[8]);
                acc[9]  = fma2(tb, w45.x, acc[9]);
                acc[10] = fma2(ta, w45.y, acc[10]);
                acc[11] = fma2(tb, w45.y, acc[11]);
                acc[12] = fma2(ta, w67.x, acc[12]);
                acc[13] = fma2(tb, w67.x, acc[13]);
                acc[14] = fma2(ta, w67.y, acc[14]);
                acc[15] = fma2(tb, w67.y, acc[15]);
            }
        }
    }

    // ---- 4-level butterfly half-exchange over the 16 q-groups
    // levels: mask = 2<<lvl exchanges q bit lvl; idx bit (3-lvl... see mapping)
#pragma unroll
    for (int lvl = 0; lvl < 4; lvl++) {
        const int mask = 2 << lvl;
        const int half = 8 >> lvl;
        const bool bit = (q >> lvl) & 1;
#pragma unroll
        for (int j = 0; j < 8; j++) {
            if (j < half) {
                u64 lo = acc[j], hi = acc[half + j];
                u64 sent = bit ? lo : hi;
                u64 rec  = __shfl_xor_sync(0xffffffffu, sent, mask);
                acc[j] = add2(bit ? hi : lo, rec);
            }
        }
    }
    // lane (q,sub) holds acc[0] = the px-pair for:
    //   idx bit3(=o bit2)<->q bit0, bit2(=o bit1)<->q bit1,
    //   bit1(=o bit0)<->q bit2, bit0(=pair)<->q bit3
    const int o    = ((q & 1) << 2) | (q & 2) | ((q >> 2) & 1);
    const int pair = (q >> 3) & 1;

    float v0, v1;
    unpack2(acc[0], v0, v1);
    const float bo = bsh[o];
    const int oy  = y0 + sy;
    const int ox0 = x0 + 4 * sxs + 2 * pair;
    if (oy < HO_) {
        float* op = out + ((b * OUT_ + o) * HO_ + oy) * WO_ + ox0;
        if (ox0 < WO_)     op[0] = v0 + bo;
        if (ox0 + 1 < WO_) op[1] = v1 + bo;
    }
}

// ---------------------------------------------------------------------------
extern "C" void kernel_launch(void* const* d_in, const int* in_sizes, int n_in,
                              void* d_out, int out_size) {
    const float* x          = (const float*)d_in[0];
    const float* phase_low  = (const float*)d_in[1];
    const float* phase_high = (const float*)d_in[2];
    const float* weight     = (const float*)d_in[3];
    const float* bias       = (const float*)d_in[4];
    float* out = (float*)d_out;

    dim3 grid(4, 8, B_);                 // 256 blocks x 512 threads, one wave
    kan_fused_kernel<<<grid, NTHR>>>(x, phase_low, phase_high, weight, bias, out);
}